// round 1
// baseline (speedup 1.0000x reference)
#include <cuda_runtime.h>
#include <cstdint>

#define B_    4
#define C_    64
#define H_    128
#define W_    128
#define HW_   16384
#define COUT_ 64
#define KK_   9
#define SP    132   // padded floats per s-row (132*4 = 528 bytes, 16B aligned)

// Scratch (allocation-free rule: __device__ globals)
__device__ float g_xT[(size_t)B_ * HW_ * C_];     // NHWC: [(b*HW + pix)*64 + c]
__device__ float g_wT[KK_ * C_ * COUT_];          // [k][c][co]

// ---------------- f32x2 packed helpers ----------------
__device__ __forceinline__ unsigned long long pk2(float lo, float hi) {
    unsigned long long r;
    asm("mov.b64 %0, {%1,%2};" : "=l"(r) : "f"(lo), "f"(hi));
    return r;
}
__device__ __forceinline__ void upk2(unsigned long long v, float& lo, float& hi) {
    asm("mov.b64 {%0,%1}, %2;" : "=f"(lo), "=f"(hi) : "l"(v));
}
__device__ __forceinline__ unsigned long long ffma2(unsigned long long a,
                                                    unsigned long long b,
                                                    unsigned long long c) {
    unsigned long long d;
    asm("fma.rn.f32x2 %0, %1, %2, %3;" : "=l"(d) : "l"(a), "l"(b), "l"(c));
    return d;
}

// ---------------- prepass: NCHW -> NHWC ----------------
__global__ void transpose_x_kernel(const float* __restrict__ x) {
    __shared__ float tile[32][33];
    const int b    = blockIdx.z;
    const int pix0 = blockIdx.x * 32;
    const int c0   = blockIdx.y * 32;
    const int tx = threadIdx.x, ty = threadIdx.y;
#pragma unroll
    for (int i = 0; i < 32; i += 8)
        tile[ty + i][tx] = x[(size_t)(b * C_ + c0 + ty + i) * HW_ + pix0 + tx];
    __syncthreads();
#pragma unroll
    for (int i = 0; i < 32; i += 8)
        g_xT[(size_t)(b * HW_ + pix0 + ty + i) * C_ + c0 + tx] = tile[tx][ty + i];
}

// weight [co][c][3][3] -> wT [k][c][co]
__global__ void transpose_w_kernel(const float* __restrict__ w) {
    int t = blockIdx.x * blockDim.x + threadIdx.x;
    if (t < KK_ * C_ * COUT_) {
        int k  = t >> 12;
        int r  = t & 4095;
        int c  = r >> 6;
        int co = r & 63;
        g_wT[t] = w[co * (C_ * KK_) + c * KK_ + k];
    }
}

// ---------------- fused deformable conv ----------------
// Grid: 512 blocks (one per (b, ho) output row). Block: 256 threads.
// smem: s[64][SP] sampled tile (XOR-swizzled p), ws2[64][128] pair-duplicated
// weights, sidx/sw[4][128] bilinear corner indices/weights.
__global__ __launch_bounds__(256, 3) void deform_main_kernel(
    const float* __restrict__ offset,
    const float* __restrict__ mask,
    const float* __restrict__ bias,
    float* __restrict__ out) {
    extern __shared__ float sm[];
    float* s    = sm;                       // 64*SP floats
    float* ws2  = sm + 64 * SP;             // 64*128 floats
    int*   sidx = (int*)(ws2 + 64 * 128);   // 4*128 ints
    float* sw   = (float*)(sidx + 4 * 128); // 4*128 floats

    const int tid = threadIdx.x;
    const int blk = blockIdx.x;       // 0..511
    const int b   = blk >> 7;
    const int ho  = blk & 127;

    const int ty = tid >> 5;          // 0..7  -> co0 = ty*8
    const int tx = tid & 31;          // 0..31 -> p0  = tx*4

    const float* __restrict__ xb = g_xT + (size_t)b * (HW_ * C_);

    // accumulators: 8 co x 4 p as 8x2 packed f32x2, bias-initialized
    unsigned long long acc[8][2];
#pragma unroll
    for (int i = 0; i < 8; ++i) {
        float bv = bias[ty * 8 + i];
        unsigned long long p = pk2(bv, bv);
        acc[i][0] = p;
        acc[i][1] = p;
    }

    for (int k = 0; k < KK_; ++k) {
        // ---- stage weights (pair-duplicated for f32x2 broadcast) ----
        const float* wk = g_wT + k * (C_ * COUT_);
#pragma unroll
        for (int i = 0; i < 16; ++i) {
            int idx = tid + 256 * i;          // idx = c*64 + co
            float v = wk[idx];
            *(float2*)&ws2[2 * idx] = make_float2(v, v);
        }

        // ---- bilinear coords for the 128 pixels of this row ----
        if (tid < 128) {
            const int p  = tid;
            const int wo = p;
            int obase = ((b * 18 + 2 * k) * 128 + ho) * 128 + wo;
            float dy = offset[obase];
            float dx = offset[obase + HW_];   // channel 2k+1
            float m  = mask[((b * 9 + k) * 128 + ho) * 128 + wo];
            float yy = (float)(ho - 1 + (k / 3)) + dy;
            float xx = (float)(wo - 1 + (k % 3)) + dx;
            float y0f = floorf(yy), x0f = floorf(xx);
            float ly = yy - y0f, lx = xx - x0f;
            int y0 = (int)y0f, x0 = (int)x0f;
            int y1 = y0 + 1,   x1 = x0 + 1;
            bool vy0 = (y0 >= 0) & (y0 < H_), vy1 = (y1 >= 0) & (y1 < H_);
            bool vx0 = (x0 >= 0) & (x0 < W_), vx1 = (x1 >= 0) & (x1 < W_);
            int cy0 = min(max(y0, 0), H_ - 1), cy1 = min(max(y1, 0), H_ - 1);
            int cx0 = min(max(x0, 0), W_ - 1), cx1 = min(max(x1, 0), W_ - 1);
            float w00 = (1.f - ly) * (1.f - lx) * m;
            float w01 = (1.f - ly) * lx * m;
            float w10 = ly * (1.f - lx) * m;
            float w11 = ly * lx * m;
            sw[0 * 128 + p] = (vy0 & vx0) ? w00 : 0.f;
            sw[1 * 128 + p] = (vy0 & vx1) ? w01 : 0.f;
            sw[2 * 128 + p] = (vy1 & vx0) ? w10 : 0.f;
            sw[3 * 128 + p] = (vy1 & vx1) ? w11 : 0.f;
            sidx[0 * 128 + p] = (cy0 * W_ + cx0) * C_;
            sidx[1 * 128 + p] = (cy0 * W_ + cx1) * C_;
            sidx[2 * 128 + p] = (cy1 * W_ + cx0) * C_;
            sidx[3 * 128 + p] = (cy1 * W_ + cx1) * C_;
        }
        __syncthreads();

        // ---- sample: channel-vectorized gathers, swizzled STS ----
#pragma unroll
        for (int it = 0; it < 8; ++it) {
            int u  = tid + 256 * it;   // 16 c4 x 128 p; warp = 16 c4 x 2 p
            int c4 = u & 15;
            int p  = u >> 4;
            float w0 = sw[p], w1 = sw[128 + p], w2 = sw[256 + p], w3 = sw[384 + p];
            int  i0 = sidx[p], i1 = sidx[128 + p], i2 = sidx[256 + p], i3 = sidx[384 + p];
            const float* xc = xb + c4 * 4;
            float4 a0 = *(const float4*)(xc + i0);
            float4 a1 = *(const float4*)(xc + i1);
            float4 a2 = *(const float4*)(xc + i2);
            float4 a3 = *(const float4*)(xc + i3);
            float v0 = w0 * a0.x + w1 * a1.x + w2 * a2.x + w3 * a3.x;
            float v1 = w0 * a0.y + w1 * a1.y + w2 * a2.y + w3 * a3.y;
            float v2 = w0 * a0.z + w1 * a1.z + w2 * a2.z + w3 * a3.z;
            float v3 = w0 * a0.w + w1 * a1.w + w2 * a2.w + w3 * a3.w;
            int pp = p ^ ((c4 & 7) << 2);    // XOR swizzle (float4-granular)
            int c  = c4 * 4;
            s[(c + 0) * SP + pp] = v0;
            s[(c + 1) * SP + pp] = v1;
            s[(c + 2) * SP + pp] = v2;
            s[(c + 3) * SP + pp] = v3;
        }
        __syncthreads();

        // ---- f32x2 register-tiled GEMM: acc[8co][4p] += w[c] * s[c][p] ----
#pragma unroll 4
        for (int c = 0; c < 64; ++c) {
            int bo = (tx ^ ((c >> 2) & 7)) << 2;   // de-swizzle read
            ulonglong2 bv = *(const ulonglong2*)&s[c * SP + bo];
            const ulonglong2* arow = (const ulonglong2*)&ws2[c * 128 + ty * 16];
            ulonglong2 a0 = arow[0], a1 = arow[1], a2 = arow[2], a3 = arow[3];
            unsigned long long bx = bv.x, by = bv.y;
#define GACC(i, aa) { acc[i][0] = ffma2(aa, bx, acc[i][0]); acc[i][1] = ffma2(aa, by, acc[i][1]); }
            GACC(0, a0.x) GACC(1, a0.y) GACC(2, a1.x) GACC(3, a1.y)
            GACC(4, a2.x) GACC(5, a2.y) GACC(6, a3.x) GACC(7, a3.y)
#undef GACC
        }
        __syncthreads();
    }

    // ---- epilogue: coalesced float4 stores ----
    float* ob = out + (size_t)(b * COUT_ + ty * 8) * HW_ + ho * W_ + tx * 4;
#pragma unroll
    for (int i = 0; i < 8; ++i) {
        float4 r;
        upk2(acc[i][0], r.x, r.y);
        upk2(acc[i][1], r.z, r.w);
        *(float4*)(ob + (size_t)i * HW_) = r;
    }
}

extern "C" void kernel_launch(void* const* d_in, const int* in_sizes, int n_in,
                              void* d_out, int out_size) {
    const float* x      = (const float*)d_in[0];
    const float* offset = (const float*)d_in[1];
    const float* mask   = (const float*)d_in[2];
    const float* weight = (const float*)d_in[3];
    const float* bias   = (const float*)d_in[4];
    float* out = (float*)d_out;

    // prepass
    transpose_x_kernel<<<dim3(HW_ / 32, C_ / 32, B_), dim3(32, 8)>>>(x);
    transpose_w_kernel<<<(KK_ * C_ * COUT_ + 255) / 256, 256>>>(weight);

    // fused main kernel
    const int smem_bytes = (64 * SP + 64 * 128 + 4 * 128) * 4 + 4 * 128 * 4; // 70656
    cudaFuncSetAttribute(deform_main_kernel,
                         cudaFuncAttributeMaxDynamicSharedMemorySize, smem_bytes);
    deform_main_kernel<<<B_ * H_, 256, smem_bytes>>>(offset, mask, bias, out);
}

// round 3
// speedup vs baseline: 2.1109x; 2.1109x over previous
#include <cuda_runtime.h>
#include <cuda_bf16.h>
#include <cstdint>

#define B_    4
#define C_    64
#define H_    128
#define W_    128
#define HW_   16384
#define COUT_ 64
#define KK_   9

// ---- smem byte layout ----
// S tiles: 128 rows x 128B (64 bf16), XOR-swizzled at 16B granularity
#define S_HI_OFF   0
#define S_LO_OFF   16384
#define W_OFF      32768      // W hi [64co][128B] then W lo, 8KB each
#define SW_OFF     49152      // bilinear corner weights 4x128 f32
#define SIDX_OFF   51200      // bilinear corner indices 4x128 i32
#define SMEM_BYTES 53248

// ---- scratch (__device__ globals: allocation-free rule) ----
__device__ float g_xT[(size_t)B_ * HW_ * C_];                    // NHWC
__device__ __align__(16) unsigned char g_w[KK_ * 16384];         // per tap: hi 8KB | lo 8KB, pre-swizzled

// ---------------- helpers ----------------
__device__ __forceinline__ uint32_t smem_u32(const void* p) {
    uint32_t a;
    asm("{ .reg .u64 t; cvta.to.shared.u64 t, %1; cvt.u32.u64 %0, t; }" : "=r"(a) : "l"(p));
    return a;
}
// pack {lo, hi} floats into bf16x2 (lo -> low 16 bits)
__device__ __forceinline__ uint32_t pack_bf16(float lo, float hi) {
    uint32_t r;
    asm("cvt.rn.bf16x2.f32 %0, %1, %2;" : "=r"(r) : "f"(hi), "f"(lo));
    return r;
}
__device__ __forceinline__ void ldsm_x4(uint32_t* r, uint32_t addr) {
    asm volatile("ldmatrix.sync.aligned.m8n8.x4.shared.b16 {%0,%1,%2,%3}, [%4];"
                 : "=r"(r[0]), "=r"(r[1]), "=r"(r[2]), "=r"(r[3]) : "r"(addr));
}
__device__ __forceinline__ void mma_bf16(float* d, const uint32_t* a, uint32_t b0, uint32_t b1) {
    asm volatile(
        "mma.sync.aligned.m16n8k16.row.col.f32.bf16.bf16.f32 "
        "{%0,%1,%2,%3}, {%4,%5,%6,%7}, {%8,%9}, {%0,%1,%2,%3};"
        : "+f"(d[0]), "+f"(d[1]), "+f"(d[2]), "+f"(d[3])
        : "r"(a[0]), "r"(a[1]), "r"(a[2]), "r"(a[3]), "r"(b0), "r"(b1));
}

// ---------------- prepass: NCHW -> NHWC ----------------
__global__ void transpose_x_kernel(const float* __restrict__ x) {
    __shared__ float tile[32][33];
    const int b    = blockIdx.z;
    const int pix0 = blockIdx.x * 32;
    const int c0   = blockIdx.y * 32;
    const int tx = threadIdx.x, ty = threadIdx.y;
#pragma unroll
    for (int i = 0; i < 32; i += 8)
        tile[ty + i][tx] = x[(size_t)(b * C_ + c0 + ty + i) * HW_ + pix0 + tx];
    __syncthreads();
#pragma unroll
    for (int i = 0; i < 32; i += 8)
        g_xT[(size_t)(b * HW_ + pix0 + ty + i) * C_ + c0 + tx] = tile[tx][ty + i];
}

// ---------------- prepass: weight -> bf16 hi/lo, swizzled [k][co][c] ----------------
__global__ void prep_w_kernel(const float* __restrict__ w) {
    int t = blockIdx.x * blockDim.x + threadIdx.x;
    if (t >= KK_ * COUT_ * C_) return;
    int k  = t >> 12;
    int r  = t & 4095;
    int co = r >> 6;
    int c  = r & 63;
    float v = w[co * (C_ * KK_) + c * KK_ + k];
    __nv_bfloat16 hb = __float2bfloat16_rn(v);
    float lo = v - __bfloat162float(hb);
    __nv_bfloat16 lb = __float2bfloat16_rn(lo);
    int jsw  = (c >> 3) ^ (co & 7);                      // 16B-chunk swizzle
    int off  = co * 128 + jsw * 16 + (c & 7) * 2;
    unsigned char* tap = g_w + k * 16384;
    *(__nv_bfloat16*)(tap + off)        = hb;
    *(__nv_bfloat16*)(tap + 8192 + off) = lb;
}

// ---------------- fused deformable conv ----------------
// One CTA per (b, ho) output row. 256 threads = 8 warps.
// GEMM: D[p=128][co=64] += S[p][c] * W[co][c], emulated fp32 via bf16x3 mma.sync.
// Warp tiles: 4 M-warps x 2 N-warps, each 32p x 32co.
__global__ __launch_bounds__(256, 2) void deform_main_kernel(
    const float* __restrict__ offset,
    const float* __restrict__ mask,
    const float* __restrict__ bias,
    float* __restrict__ out) {
    extern __shared__ char sm[];
    const uint32_t smb = smem_u32(sm);
    float* sw   = (float*)(sm + SW_OFF);
    int*   sidx = (int*)(sm + SIDX_OFF);

    const int tid = threadIdx.x;
    const int wid = tid >> 5;
    const int l   = tid & 31;
    const int blk = blockIdx.x;
    const int b   = blk >> 7;
    const int ho  = blk & 127;

    const float* __restrict__ xb = g_xT + (size_t)b * (HW_ * C_);

    // per-warp GEMM constants
    const int pm0 = (wid & 3) * 32;          // pixel block
    const int co0 = (wid >> 2) * 32;         // cout block
    const int lrow = l & 15, lhi = l >> 4, lm = lrow & 7;
    const uint32_t aAd0 = smb + (uint32_t)(pm0 + lrow) * 128;
    const uint32_t aAd1 = aAd0 + 16 * 128;
    const uint32_t bAd0 = smb + W_OFF + (uint32_t)(co0 + lrow) * 128;
    const uint32_t bAd1 = bAd0 + 16 * 128;

    float acc[2][4][4];
#pragma unroll
    for (int i = 0; i < 2; ++i)
#pragma unroll
        for (int j = 0; j < 4; ++j)
#pragma unroll
            for (int q = 0; q < 4; ++q) acc[i][j][q] = 0.f;

    for (int k = 0; k < KK_; ++k) {
        // ---- stage this tap's weights (raw copy preserves swizzle) ----
        {
            const float4* wg  = (const float4*)(g_w + k * 16384);
            float4*       wsm = (float4*)(sm + W_OFF);
#pragma unroll
            for (int i = 0; i < 4; ++i) wsm[tid + 256 * i] = wg[tid + 256 * i];
        }
        // ---- bilinear coords for the 128 pixels of this row ----
        if (tid < 128) {
            const int p  = tid;
            const int wo = p;
            int obase = ((b * 18 + 2 * k) * 128 + ho) * 128 + wo;
            float dy = offset[obase];
            float dx = offset[obase + HW_];
            float m  = mask[((b * 9 + k) * 128 + ho) * 128 + wo];
            float yy = (float)(ho - 1 + (k / 3)) + dy;
            float xx = (float)(wo - 1 + (k % 3)) + dx;
            float y0f = floorf(yy), x0f = floorf(xx);
            float ly = yy - y0f, lx = xx - x0f;
            int y0 = (int)y0f, x0 = (int)x0f;
            int y1 = y0 + 1,   x1 = x0 + 1;
            bool vy0 = (y0 >= 0) & (y0 < H_), vy1 = (y1 >= 0) & (y1 < H_);
            bool vx0 = (x0 >= 0) & (x0 < W_), vx1 = (x1 >= 0) & (x1 < W_);
            int cy0 = min(max(y0, 0), H_ - 1), cy1 = min(max(y1, 0), H_ - 1);
            int cx0 = min(max(x0, 0), W_ - 1), cx1 = min(max(x1, 0), W_ - 1);
            float w00 = (1.f - ly) * (1.f - lx) * m;
            float w01 = (1.f - ly) * lx * m;
            float w10 = ly * (1.f - lx) * m;
            float w11 = ly * lx * m;
            sw[0 * 128 + p] = (vy0 & vx0) ? w00 : 0.f;
            sw[1 * 128 + p] = (vy0 & vx1) ? w01 : 0.f;
            sw[2 * 128 + p] = (vy1 & vx0) ? w10 : 0.f;
            sw[3 * 128 + p] = (vy1 & vx1) ? w11 : 0.f;
            sidx[0 * 128 + p] = (cy0 * W_ + cx0) * C_;
            sidx[1 * 128 + p] = (cy0 * W_ + cx1) * C_;
            sidx[2 * 128 + p] = (cy1 * W_ + cx0) * C_;
            sidx[3 * 128 + p] = (cy1 * W_ + cx1) * C_;
        }
        __syncthreads();

        // ---- sample + bf16 hi/lo split -> swizzled S tiles ----
#pragma unroll
        for (int it = 0; it < 8; ++it) {
            int u  = tid + 256 * it;   // 16 c4-groups x 128 pixels
            int c4 = u & 15;
            int p  = u >> 4;
            float w0 = sw[p], w1 = sw[128 + p], w2 = sw[256 + p], w3 = sw[384 + p];
            int  i0 = sidx[p], i1 = sidx[128 + p], i2 = sidx[256 + p], i3 = sidx[384 + p];
            const float* xc = xb + c4 * 4;
            float4 a0 = *(const float4*)(xc + i0);
            float4 a1 = *(const float4*)(xc + i1);
            float4 a2 = *(const float4*)(xc + i2);
            float4 a3 = *(const float4*)(xc + i3);
            float v0 = w0 * a0.x + w1 * a1.x + w2 * a2.x + w3 * a3.x;
            float v1 = w0 * a0.y + w1 * a1.y + w2 * a2.y + w3 * a3.y;
            float v2 = w0 * a0.z + w1 * a1.z + w2 * a2.z + w3 * a3.z;
            float v3 = w0 * a0.w + w1 * a1.w + w2 * a2.w + w3 * a3.w;
            uint32_t h01 = pack_bf16(v0, v1);
            uint32_t h23 = pack_bf16(v2, v3);
            float l0 = v0 - __uint_as_float(h01 << 16);
            float l1 = v1 - __uint_as_float(h01 & 0xFFFF0000u);
            float l2 = v2 - __uint_as_float(h23 << 16);
            float l3 = v3 - __uint_as_float(h23 & 0xFFFF0000u);
            uint32_t q01 = pack_bf16(l0, l1);
            uint32_t q23 = pack_bf16(l2, l3);
            int jsw = (c4 >> 1) ^ (p & 7);
            uint32_t off = (uint32_t)(p * 128 + jsw * 16 + (c4 & 1) * 8);
            *(uint2*)(sm + S_HI_OFF + off) = make_uint2(h01, h23);
            *(uint2*)(sm + S_LO_OFF + off) = make_uint2(q01, q23);
        }
        __syncthreads();

        // ---- bf16x3 GEMM via mma.sync ----
#pragma unroll
        for (int ks = 0; ks < 4; ++ks) {
            const uint32_t soff = (uint32_t)((((ks << 1) | lhi) ^ lm) << 4);
            uint32_t ah0[4], ah1[4], bh0[4], bh1[4];
            ldsm_x4(ah0, aAd0 + soff);
            ldsm_x4(ah1, aAd1 + soff);
            ldsm_x4(bh0, bAd0 + soff);
            ldsm_x4(bh1, bAd1 + soff);
            // Shi * Whi
            mma_bf16(acc[0][0], ah0, bh0[0], bh0[2]);
            mma_bf16(acc[0][1], ah0, bh0[1], bh0[3]);
            mma_bf16(acc[0][2], ah0, bh1[0], bh1[2]);
            mma_bf16(acc[0][3], ah0, bh1[1], bh1[3]);
            mma_bf16(acc[1][0], ah1, bh0[0], bh0[2]);
            mma_bf16(acc[1][1], ah1, bh0[1], bh0[3]);
            mma_bf16(acc[1][2], ah1, bh1[0], bh1[2]);
            mma_bf16(acc[1][3], ah1, bh1[1], bh1[3]);
            // Shi * Wlo
            uint32_t bl0[4], bl1[4];
            ldsm_x4(bl0, bAd0 + 8192 + soff);
            ldsm_x4(bl1, bAd1 + 8192 + soff);
            mma_bf16(acc[0][0], ah0, bl0[0], bl0[2]);
            mma_bf16(acc[0][1], ah0, bl0[1], bl0[3]);
            mma_bf16(acc[0][2], ah0, bl1[0], bl1[2]);
            mma_bf16(acc[0][3], ah0, bl1[1], bl1[3]);
            mma_bf16(acc[1][0], ah1, bl0[0], bl0[2]);
            mma_bf16(acc[1][1], ah1, bl0[1], bl0[3]);
            mma_bf16(acc[1][2], ah1, bl1[0], bl1[2]);
            mma_bf16(acc[1][3], ah1, bl1[1], bl1[3]);
            // Slo * Whi
            uint32_t al0[4], al1[4];
            ldsm_x4(al0, aAd0 + 16384 + soff);
            ldsm_x4(al1, aAd1 + 16384 + soff);
            mma_bf16(acc[0][0], al0, bh0[0], bh0[2]);
            mma_bf16(acc[0][1], al0, bh0[1], bh0[3]);
            mma_bf16(acc[0][2], al0, bh1[0], bh1[2]);
            mma_bf16(acc[0][3], al0, bh1[1], bh1[3]);
            mma_bf16(acc[1][0], al1, bh0[0], bh0[2]);
            mma_bf16(acc[1][1], al1, bh0[1], bh0[3]);
            mma_bf16(acc[1][2], al1, bh1[0], bh1[2]);
            mma_bf16(acc[1][3], al1, bh1[1], bh1[3]);
        }
        __syncthreads();   // protect S and W from next tap's overwrite
    }

    // ---- epilogue: d-fragment -> gmem, add bias ----
    // fragment: d0 (row r, col c), d1 (r, c+1), d2 (r+8, c), d3 (r+8, c+1)
    const int rr = (l >> 2);
    const int cbase = (l & 3) * 2;
#pragma unroll
    for (int j = 0; j < 4; ++j) {
        int cc = co0 + j * 8 + cbase;
        float b0v = bias[cc], b1v = bias[cc + 1];
        size_t o0 = ((size_t)(b * COUT_ + cc) * 128 + ho) * 128;
        size_t o1 = o0 + (size_t)HW_;
#pragma unroll
        for (int mi = 0; mi < 2; ++mi) {
            int r0 = pm0 + mi * 16 + rr;
            out[o0 + r0]     = acc[mi][j][0] + b0v;
            out[o1 + r0]     = acc[mi][j][1] + b1v;
            out[o0 + r0 + 8] = acc[mi][j][2] + b0v;
            out[o1 + r0 + 8] = acc[mi][j][3] + b1v;
        }
    }
}

extern "C" void kernel_launch(void* const* d_in, const int* in_sizes, int n_in,
                              void* d_out, int out_size) {
    const float* x      = (const float*)d_in[0];
    const float* offset = (const float*)d_in[1];
    const float* mask   = (const float*)d_in[2];
    const float* weight = (const float*)d_in[3];
    const float* bias   = (const float*)d_in[4];
    float* out = (float*)d_out;

    transpose_x_kernel<<<dim3(HW_ / 32, C_ / 32, B_), dim3(32, 8)>>>(x);
    prep_w_kernel<<<(KK_ * C_ * COUT_ + 255) / 256, 256>>>(weight);

    cudaFuncSetAttribute(deform_main_kernel,
                         cudaFuncAttributeMaxDynamicSharedMemorySize, SMEM_BYTES);
    deform_main_kernel<<<B_ * H_, 256, SMEM_BYTES>>>(offset, mask, bias, out);
}

// round 4
// speedup vs baseline: 2.1361x; 1.0119x over previous
#include <cuda_runtime.h>
#include <cuda_bf16.h>
#include <cstdint>

#define B_    4
#define C_    64
#define H_    128
#define W_    128
#define HW_   16384
#define COUT_ 64
#define KK_   9

// ---- smem byte layout ----
#define S_HI_OFF   0          // 256 rows x 128B (64 bf16), XOR-swizzled 16B granules
#define S_LO_OFF   32768
#define W0_OFF     65536      // W buf0: hi 8KB | lo 8KB
#define W1_OFF     81920      // W buf1
#define SW_OFF     98304      // bilinear corner weights 4x256 f32
#define SIDX_OFF   102400     // bilinear corner indices 4x256 i32
#define SMEM_BYTES 106496

// ---- scratch (__device__ globals: allocation-free rule) ----
__device__ float g_xT[(size_t)B_ * HW_ * C_];                    // NHWC
__device__ __align__(16) unsigned char g_w[KK_ * 16384];         // per tap: hi 8KB | lo 8KB, pre-swizzled

// ---------------- helpers ----------------
__device__ __forceinline__ uint32_t smem_u32(const void* p) {
    uint32_t a;
    asm("{ .reg .u64 t; cvta.to.shared.u64 t, %1; cvt.u32.u64 %0, t; }" : "=r"(a) : "l"(p));
    return a;
}
__device__ __forceinline__ uint32_t pack_bf16(float lo, float hi) {
    uint32_t r;
    asm("cvt.rn.bf16x2.f32 %0, %1, %2;" : "=r"(r) : "f"(hi), "f"(lo));
    return r;
}
__device__ __forceinline__ void ldsm_x4(uint32_t* r, uint32_t addr) {
    asm volatile("ldmatrix.sync.aligned.m8n8.x4.shared.b16 {%0,%1,%2,%3}, [%4];"
                 : "=r"(r[0]), "=r"(r[1]), "=r"(r[2]), "=r"(r[3]) : "r"(addr));
}
__device__ __forceinline__ void mma_bf16(float* d, const uint32_t* a, uint32_t b0, uint32_t b1) {
    asm volatile(
        "mma.sync.aligned.m16n8k16.row.col.f32.bf16.bf16.f32 "
        "{%0,%1,%2,%3}, {%4,%5,%6,%7}, {%8,%9}, {%0,%1,%2,%3};"
        : "+f"(d[0]), "+f"(d[1]), "+f"(d[2]), "+f"(d[3])
        : "r"(a[0]), "r"(a[1]), "r"(a[2]), "r"(a[3]), "r"(b0), "r"(b1));
}
__device__ __forceinline__ void cp_async16(uint32_t dst, const void* src) {
    asm volatile("cp.async.ca.shared.global [%0], [%1], 16;" :: "r"(dst), "l"(src) : "memory");
}

// ---------------- prepass: NCHW -> NHWC ----------------
__global__ void transpose_x_kernel(const float* __restrict__ x) {
    __shared__ float tile[32][33];
    const int b    = blockIdx.z;
    const int pix0 = blockIdx.x * 32;
    const int c0   = blockIdx.y * 32;
    const int tx = threadIdx.x, ty = threadIdx.y;
#pragma unroll
    for (int i = 0; i < 32; i += 8)
        tile[ty + i][tx] = x[(size_t)(b * C_ + c0 + ty + i) * HW_ + pix0 + tx];
    __syncthreads();
#pragma unroll
    for (int i = 0; i < 32; i += 8)
        g_xT[(size_t)(b * HW_ + pix0 + ty + i) * C_ + c0 + tx] = tile[tx][ty + i];
}

// ---------------- prepass: weight -> bf16 hi/lo, swizzled [k][co][c] ----------------
__global__ void prep_w_kernel(const float* __restrict__ w) {
    int t = blockIdx.x * blockDim.x + threadIdx.x;
    if (t >= KK_ * COUT_ * C_) return;
    int k  = t >> 12;
    int r  = t & 4095;
    int co = r >> 6;
    int c  = r & 63;
    float v = w[co * (C_ * KK_) + c * KK_ + k];
    __nv_bfloat16 hb = __float2bfloat16_rn(v);
    float lo = v - __bfloat162float(hb);
    __nv_bfloat16 lb = __float2bfloat16_rn(lo);
    int jsw  = (c >> 3) ^ (co & 7);
    int off  = co * 128 + jsw * 16 + (c & 7) * 2;
    unsigned char* tap = g_w + k * 16384;
    *(__nv_bfloat16*)(tap + off)        = hb;
    *(__nv_bfloat16*)(tap + 8192 + off) = lb;
}

// ---------------- fused deformable conv ----------------
// One CTA per (b, ho-pair): M = 256 pixels (2 output rows) x 64 cout. 256 threads.
// Pipeline: sample(k) | sync | [cp.async W(k+1) + coords(k+1) + GEMM(k)] | sync.
__global__ __launch_bounds__(256, 2) void deform_main_kernel(
    const float* __restrict__ offset,
    const float* __restrict__ mask,
    const float* __restrict__ bias,
    float* __restrict__ out) {
    extern __shared__ char sm[];
    const uint32_t smb = smem_u32(sm);
    float* sw   = (float*)(sm + SW_OFF);
    int*   sidx = (int*)(sm + SIDX_OFF);

    const int tid = threadIdx.x;
    const int wid = tid >> 5;
    const int l   = tid & 31;
    const int blk = blockIdx.x;          // 0..255
    const int b   = blk >> 6;
    const int ho0 = (blk & 63) * 2;

    const float* __restrict__ xb = g_xT + (size_t)b * (HW_ * C_);

    // per-warp GEMM constants: 4 M-warps x 2 N-warps; tile 64px x 32co
    const int pm0 = (wid & 3) * 64;
    const int co0 = (wid >> 2) * 32;
    const int lrow = l & 15, lhi = l >> 4, lm = lrow & 7;

    float acc[4][4][4];
#pragma unroll
    for (int i = 0; i < 4; ++i)
#pragma unroll
        for (int j = 0; j < 4; ++j)
#pragma unroll
            for (int q = 0; q < 4; ++q) acc[i][j][q] = 0.f;

    // ---- coords for tap k (thread = 1 pixel of 256) ----
    auto coords = [&](int k) {
        const int p   = tid;
        const int row = p >> 7;
        const int ho  = ho0 + row;
        const int wo  = p & 127;
        int obase = ((b * 18 + 2 * k) * 128 + ho) * 128 + wo;
        float dy = offset[obase];
        float dx = offset[obase + HW_];
        float m  = mask[((b * 9 + k) * 128 + ho) * 128 + wo];
        float yy = (float)(ho - 1 + (k / 3)) + dy;
        float xx = (float)(wo - 1 + (k % 3)) + dx;
        float y0f = floorf(yy), x0f = floorf(xx);
        float ly = yy - y0f, lx = xx - x0f;
        int y0 = (int)y0f, x0 = (int)x0f;
        int y1 = y0 + 1,   x1 = x0 + 1;
        bool vy0 = (y0 >= 0) & (y0 < H_), vy1 = (y1 >= 0) & (y1 < H_);
        bool vx0 = (x0 >= 0) & (x0 < W_), vx1 = (x1 >= 0) & (x1 < W_);
        int cy0 = min(max(y0, 0), H_ - 1), cy1 = min(max(y1, 0), H_ - 1);
        int cx0 = min(max(x0, 0), W_ - 1), cx1 = min(max(x1, 0), W_ - 1);
        float w00 = (1.f - ly) * (1.f - lx) * m;
        float w01 = (1.f - ly) * lx * m;
        float w10 = ly * (1.f - lx) * m;
        float w11 = ly * lx * m;
        sw[0 * 256 + p] = (vy0 & vx0) ? w00 : 0.f;
        sw[1 * 256 + p] = (vy0 & vx1) ? w01 : 0.f;
        sw[2 * 256 + p] = (vy1 & vx0) ? w10 : 0.f;
        sw[3 * 256 + p] = (vy1 & vx1) ? w11 : 0.f;
        sidx[0 * 256 + p] = (cy0 * W_ + cx0) * C_;
        sidx[1 * 256 + p] = (cy0 * W_ + cx1) * C_;
        sidx[2 * 256 + p] = (cy1 * W_ + cx0) * C_;
        sidx[3 * 256 + p] = (cy1 * W_ + cx1) * C_;
    };
    auto load_w = [&](int k, uint32_t woff) {
        const unsigned char* src = g_w + k * 16384 + tid * 16;
#pragma unroll
        for (int i = 0; i < 4; ++i)
            cp_async16(smb + woff + tid * 16 + i * 4096, src + i * 4096);
        asm volatile("cp.async.commit_group;" ::: "memory");
    };

    // ---- prologue: tap 0 coords + weights ----
    load_w(0, W0_OFF);
    coords(0);
    asm volatile("cp.async.wait_group 0;" ::: "memory");
    __syncthreads();

    for (int k = 0; k < KK_; ++k) {
        const uint32_t wcur = (k & 1) ? W1_OFF : W0_OFF;

        // ---- sample + bf16 hi/lo split -> swizzled S tiles ----
#pragma unroll
        for (int it = 0; it < 16; ++it) {
            int u  = tid + 256 * it;   // 16 c4-groups x 256 pixels
            int c4 = u & 15;
            int p  = u >> 4;
            float w0 = sw[p], w1 = sw[256 + p], w2 = sw[512 + p], w3 = sw[768 + p];
            int  i0 = sidx[p], i1 = sidx[256 + p], i2 = sidx[512 + p], i3 = sidx[768 + p];
            const float* xc = xb + c4 * 4;
            float4 a0 = *(const float4*)(xc + i0);
            float4 a1 = *(const float4*)(xc + i1);
            float4 a2 = *(const float4*)(xc + i2);
            float4 a3 = *(const float4*)(xc + i3);
            float v0 = w0 * a0.x + w1 * a1.x + w2 * a2.x + w3 * a3.x;
            float v1 = w0 * a0.y + w1 * a1.y + w2 * a2.y + w3 * a3.y;
            float v2 = w0 * a0.z + w1 * a1.z + w2 * a2.z + w3 * a3.z;
            float v3 = w0 * a0.w + w1 * a1.w + w2 * a2.w + w3 * a3.w;
            uint32_t h01 = pack_bf16(v0, v1);
            uint32_t h23 = pack_bf16(v2, v3);
            float l0 = v0 - __uint_as_float(h01 << 16);
            float l1 = v1 - __uint_as_float(h01 & 0xFFFF0000u);
            float l2 = v2 - __uint_as_float(h23 << 16);
            float l3 = v3 - __uint_as_float(h23 & 0xFFFF0000u);
            uint32_t q01 = pack_bf16(l0, l1);
            uint32_t q23 = pack_bf16(l2, l3);
            int jsw = (c4 >> 1) ^ (p & 7);
            uint32_t off = (uint32_t)(p * 128 + jsw * 16 + (c4 & 1) * 8);
            *(uint2*)(sm + S_HI_OFF + off) = make_uint2(h01, h23);
            *(uint2*)(sm + S_LO_OFF + off) = make_uint2(q01, q23);
        }
        __syncthreads();

        // ---- overlap: prefetch next tap's weights + coords during GEMM ----
        if (k + 1 < KK_) {
            load_w(k + 1, (k & 1) ? W0_OFF : W1_OFF);
            coords(k + 1);
        }

        // ---- bf16x3 GEMM via mma.sync ----
        const uint32_t aBase = smb + (uint32_t)(pm0 + lrow) * 128;
        const uint32_t bBase = smb + wcur + (uint32_t)(co0 + lrow) * 128;
#pragma unroll
        for (int ks = 0; ks < 4; ++ks) {
            const uint32_t soff = (uint32_t)((((ks << 1) | lhi) ^ lm) << 4);
            uint32_t bh0[4], bh1[4], bl0[4], bl1[4];
            ldsm_x4(bh0, bBase + soff);
            ldsm_x4(bh1, bBase + 2048 + soff);
            ldsm_x4(bl0, bBase + 8192 + soff);
            ldsm_x4(bl1, bBase + 10240 + soff);
#pragma unroll
            for (int mf = 0; mf < 4; ++mf) {
                const uint32_t aAd = aBase + (uint32_t)(mf * 16 * 128) + soff;
                uint32_t ah[4], al[4];
                ldsm_x4(ah, aAd);
                ldsm_x4(al, aAd + 32768 /* S_LO - S_HI */);
                // Shi*Whi
                mma_bf16(acc[mf][0], ah, bh0[0], bh0[2]);
                mma_bf16(acc[mf][1], ah, bh0[1], bh0[3]);
                mma_bf16(acc[mf][2], ah, bh1[0], bh1[2]);
                mma_bf16(acc[mf][3], ah, bh1[1], bh1[3]);
                // Shi*Wlo
                mma_bf16(acc[mf][0], ah, bl0[0], bl0[2]);
                mma_bf16(acc[mf][1], ah, bl0[1], bl0[3]);
                mma_bf16(acc[mf][2], ah, bl1[0], bl1[2]);
                mma_bf16(acc[mf][3], ah, bl1[1], bl1[3]);
                // Slo*Whi
                mma_bf16(acc[mf][0], al, bh0[0], bh0[2]);
                mma_bf16(acc[mf][1], al, bh0[1], bh0[3]);
                mma_bf16(acc[mf][2], al, bh1[0], bh1[2]);
                mma_bf16(acc[mf][3], al, bh1[1], bh1[3]);
            }
        }
        if (k + 1 < KK_)
            asm volatile("cp.async.wait_group 0;" ::: "memory");
        __syncthreads();   // protect S (and coords/W buffers) for next tap
    }

    // ---- epilogue: fragments -> gmem, add bias ----
    const int rr = (l >> 2);
    const int cbase = (l & 3) * 2;
#pragma unroll
    for (int j = 0; j < 4; ++j) {
        int cc = co0 + j * 8 + cbase;
        float b0v = bias[cc], b1v = bias[cc + 1];
        size_t plane0 = (size_t)(b * COUT_ + cc) * HW_;
        size_t plane1 = plane0 + HW_;
#pragma unroll
        for (int mf = 0; mf < 4; ++mf) {
            int px0 = pm0 + mf * 16 + rr;
            int px1 = px0 + 8;
            size_t o00 = plane0 + (size_t)(ho0 + (px0 >> 7)) * W_ + (px0 & 127);
            size_t o01 = plane1 + (size_t)(ho0 + (px0 >> 7)) * W_ + (px0 & 127);
            size_t o10 = plane0 + (size_t)(ho0 + (px1 >> 7)) * W_ + (px1 & 127);
            size_t o11 = plane1 + (size_t)(ho0 + (px1 >> 7)) * W_ + (px1 & 127);
            out[o00] = acc[mf][j][0] + b0v;
            out[o01] = acc[mf][j][1] + b1v;
            out[o10] = acc[mf][j][2] + b0v;
            out[o11] = acc[mf][j][3] + b1v;
        }
    }
}

extern "C" void kernel_launch(void* const* d_in, const int* in_sizes, int n_in,
                              void* d_out, int out_size) {
    const float* x      = (const float*)d_in[0];
    const float* offset = (const float*)d_in[1];
    const float* mask   = (const float*)d_in[2];
    const float* weight = (const float*)d_in[3];
    const float* bias   = (const float*)d_in[4];
    float* out = (float*)d_out;

    transpose_x_kernel<<<dim3(HW_ / 32, C_ / 32, B_), dim3(32, 8)>>>(x);
    prep_w_kernel<<<(KK_ * C_ * COUT_ + 255) / 256, 256>>>(weight);

    cudaFuncSetAttribute(deform_main_kernel,
                         cudaFuncAttributeMaxDynamicSharedMemorySize, SMEM_BYTES);
    deform_main_kernel<<<B_ * (H_ / 2), 256, SMEM_BYTES>>>(offset, mask, bias, out);
}

// round 5
// speedup vs baseline: 2.3812x; 1.1147x over previous
#include <cuda_runtime.h>
#include <cuda_fp16.h>
#include <cstdint>

#define B_    4
#define C_    64
#define H_    128
#define W_    128
#define HW_   16384
#define COUT_ 64
#define KK_   9

// ---- smem byte layout ----
#define S_OFF      0          // S fp16: 256 rows x 128B, XOR-swizzled 16B granules (32KB)
#define W0_OFF     32768      // W buf0: hi 8KB | lo 8KB
#define W1_OFF     49152      // W buf1
#define SW_OFF     65536      // bilinear corner weights 4x256 f32
#define SIDX_OFF   69632      // bilinear corner indices 4x256 i32
#define SMEM_BYTES 73728

// ---- scratch (__device__ globals: allocation-free rule) ----
__device__ float g_xT[(size_t)B_ * HW_ * C_];                    // NHWC
__device__ __align__(16) unsigned char g_w[KK_ * 16384];         // per tap: fp16 hi 8KB | lo 8KB, pre-swizzled

// ---------------- helpers ----------------
__device__ __forceinline__ uint32_t smem_u32(const void* p) {
    uint32_t a;
    asm("{ .reg .u64 t; cvta.to.shared.u64 t, %1; cvt.u32.u64 %0, t; }" : "=r"(a) : "l"(p));
    return a;
}
// pack {lo, hi} floats into f16x2 (lo -> low 16 bits)
__device__ __forceinline__ uint32_t pack_f16(float lo, float hi) {
    uint32_t r;
    asm("cvt.rn.f16x2.f32 %0, %1, %2;" : "=r"(r) : "f"(hi), "f"(lo));
    return r;
}
__device__ __forceinline__ void ldsm_x4(uint32_t* r, uint32_t addr) {
    asm volatile("ldmatrix.sync.aligned.m8n8.x4.shared.b16 {%0,%1,%2,%3}, [%4];"
                 : "=r"(r[0]), "=r"(r[1]), "=r"(r[2]), "=r"(r[3]) : "r"(addr));
}
__device__ __forceinline__ void mma_f16(float* d, const uint32_t* a, uint32_t b0, uint32_t b1) {
    asm volatile(
        "mma.sync.aligned.m16n8k16.row.col.f32.f16.f16.f32 "
        "{%0,%1,%2,%3}, {%4,%5,%6,%7}, {%8,%9}, {%0,%1,%2,%3};"
        : "+f"(d[0]), "+f"(d[1]), "+f"(d[2]), "+f"(d[3])
        : "r"(a[0]), "r"(a[1]), "r"(a[2]), "r"(a[3]), "r"(b0), "r"(b1));
}
__device__ __forceinline__ void cp_async16(uint32_t dst, const void* src) {
    asm volatile("cp.async.ca.shared.global [%0], [%1], 16;" :: "r"(dst), "l"(src) : "memory");
}

// ---------------- prepass: NCHW -> NHWC ----------------
__global__ void transpose_x_kernel(const float* __restrict__ x) {
    __shared__ float tile[32][33];
    const int b    = blockIdx.z;
    const int pix0 = blockIdx.x * 32;
    const int c0   = blockIdx.y * 32;
    const int tx = threadIdx.x, ty = threadIdx.y;
#pragma unroll
    for (int i = 0; i < 32; i += 8)
        tile[ty + i][tx] = x[(size_t)(b * C_ + c0 + ty + i) * HW_ + pix0 + tx];
    __syncthreads();
#pragma unroll
    for (int i = 0; i < 32; i += 8)
        g_xT[(size_t)(b * HW_ + pix0 + ty + i) * C_ + c0 + tx] = tile[tx][ty + i];
}

// ---------------- prepass: weight -> fp16 hi/lo, swizzled [k][co][c] ----------------
__global__ void prep_w_kernel(const float* __restrict__ w) {
    int t = blockIdx.x * blockDim.x + threadIdx.x;
    if (t >= KK_ * COUT_ * C_) return;
    int k  = t >> 12;
    int r  = t & 4095;
    int co = r >> 6;
    int c  = r & 63;
    float v = w[co * (C_ * KK_) + c * KK_ + k];
    __half hb = __float2half_rn(v);
    float lo = v - __half2float(hb);
    __half lb = __float2half_rn(lo);
    int jsw  = (c >> 3) ^ (co & 7);
    int off  = co * 128 + jsw * 16 + (c & 7) * 2;
    unsigned char* tap = g_w + k * 16384;
    *(__half*)(tap + off)        = hb;
    *(__half*)(tap + 8192 + off) = lb;
}

// ---------------- fused deformable conv ----------------
// One CTA per (b, ho-pair): M = 256 pixels (2 output rows) x 64 cout. 256 threads.
// GEMM: D += S_f16 * (Whi + Wlo), fp16x2-term emulated fp32 via mma.sync.
__global__ __launch_bounds__(256, 2) void deform_main_kernel(
    const float* __restrict__ offset,
    const float* __restrict__ mask,
    const float* __restrict__ bias,
    float* __restrict__ out) {
    extern __shared__ char sm[];
    const uint32_t smb = smem_u32(sm);
    float* sw   = (float*)(sm + SW_OFF);
    int*   sidx = (int*)(sm + SIDX_OFF);

    const int tid = threadIdx.x;
    const int wid = tid >> 5;
    const int l   = tid & 31;
    const int blk = blockIdx.x;          // 0..255
    const int b   = blk >> 6;
    const int ho0 = (blk & 63) * 2;

    const float* __restrict__ xb = g_xT + (size_t)b * (HW_ * C_);

    // per-warp GEMM constants: 4 M-warps x 2 N-warps; tile 64px x 32co
    const int pm0 = (wid & 3) * 64;
    const int co0 = (wid >> 2) * 32;
    const int lrow = l & 15, lhi = l >> 4, lm = lrow & 7;

    float acc[4][4][4];
#pragma unroll
    for (int i = 0; i < 4; ++i)
#pragma unroll
        for (int j = 0; j < 4; ++j)
#pragma unroll
            for (int q = 0; q < 4; ++q) acc[i][j][q] = 0.f;

    // ---- coords for tap k (thread = 1 pixel of 256) ----
    auto coords = [&](int k) {
        const int p   = tid;
        const int row = p >> 7;
        const int ho  = ho0 + row;
        const int wo  = p & 127;
        int obase = ((b * 18 + 2 * k) * 128 + ho) * 128 + wo;
        float dy = offset[obase];
        float dx = offset[obase + HW_];
        float m  = mask[((b * 9 + k) * 128 + ho) * 128 + wo];
        float yy = (float)(ho - 1 + (k / 3)) + dy;
        float xx = (float)(wo - 1 + (k % 3)) + dx;
        float y0f = floorf(yy), x0f = floorf(xx);
        float ly = yy - y0f, lx = xx - x0f;
        int y0 = (int)y0f, x0 = (int)x0f;
        int y1 = y0 + 1,   x1 = x0 + 1;
        bool vy0 = (y0 >= 0) & (y0 < H_), vy1 = (y1 >= 0) & (y1 < H_);
        bool vx0 = (x0 >= 0) & (x0 < W_), vx1 = (x1 >= 0) & (x1 < W_);
        int cy0 = min(max(y0, 0), H_ - 1), cy1 = min(max(y1, 0), H_ - 1);
        int cx0 = min(max(x0, 0), W_ - 1), cx1 = min(max(x1, 0), W_ - 1);
        float w00 = (1.f - ly) * (1.f - lx) * m;
        float w01 = (1.f - ly) * lx * m;
        float w10 = ly * (1.f - lx) * m;
        float w11 = ly * lx * m;
        sw[0 * 256 + p] = (vy0 & vx0) ? w00 : 0.f;
        sw[1 * 256 + p] = (vy0 & vx1) ? w01 : 0.f;
        sw[2 * 256 + p] = (vy1 & vx0) ? w10 : 0.f;
        sw[3 * 256 + p] = (vy1 & vx1) ? w11 : 0.f;
        sidx[0 * 256 + p] = (cy0 * W_ + cx0) * C_;
        sidx[1 * 256 + p] = (cy0 * W_ + cx1) * C_;
        sidx[2 * 256 + p] = (cy1 * W_ + cx0) * C_;
        sidx[3 * 256 + p] = (cy1 * W_ + cx1) * C_;
    };
    auto load_w = [&](int k, uint32_t woff) {
        const unsigned char* src = g_w + k * 16384 + tid * 16;
#pragma unroll
        for (int i = 0; i < 4; ++i)
            cp_async16(smb + woff + tid * 16 + i * 4096, src + i * 4096);
        asm volatile("cp.async.commit_group;" ::: "memory");
    };

    // ---- prologue: tap 0 coords + weights ----
    load_w(0, W0_OFF);
    coords(0);
    asm volatile("cp.async.wait_group 0;" ::: "memory");
    __syncthreads();

    for (int k = 0; k < KK_; ++k) {
        const uint32_t wcur = (k & 1) ? W1_OFF : W0_OFF;

        // ---- sample -> fp16 swizzled S tile ----
#pragma unroll
        for (int it = 0; it < 16; ++it) {
            int u  = tid + 256 * it;   // 16 c4-groups x 256 pixels
            int c4 = u & 15;
            int p  = u >> 4;
            float w0 = sw[p], w1 = sw[256 + p], w2 = sw[512 + p], w3 = sw[768 + p];
            int  i0 = sidx[p], i1 = sidx[256 + p], i2 = sidx[512 + p], i3 = sidx[768 + p];
            const float* xc = xb + c4 * 4;
            float4 a0 = *(const float4*)(xc + i0);
            float4 a1 = *(const float4*)(xc + i1);
            float4 a2 = *(const float4*)(xc + i2);
            float4 a3 = *(const float4*)(xc + i3);
            float v0 = w0 * a0.x + w1 * a1.x + w2 * a2.x + w3 * a3.x;
            float v1 = w0 * a0.y + w1 * a1.y + w2 * a2.y + w3 * a3.y;
            float v2 = w0 * a0.z + w1 * a1.z + w2 * a2.z + w3 * a3.z;
            float v3 = w0 * a0.w + w1 * a1.w + w2 * a2.w + w3 * a3.w;
            uint32_t h01 = pack_f16(v0, v1);
            uint32_t h23 = pack_f16(v2, v3);
            int jsw = (c4 >> 1) ^ (p & 7);
            uint32_t off = (uint32_t)(p * 128 + jsw * 16 + (c4 & 1) * 8);
            *(uint2*)(sm + S_OFF + off) = make_uint2(h01, h23);
        }
        __syncthreads();

        // ---- overlap: prefetch next tap's weights + coords during GEMM ----
        if (k + 1 < KK_) {
            load_w(k + 1, (k & 1) ? W0_OFF : W1_OFF);
            coords(k + 1);
        }

        // ---- fp16 2-term GEMM via mma.sync ----
        const uint32_t aBase = smb + (uint32_t)(pm0 + lrow) * 128;
        const uint32_t bBase = smb + wcur + (uint32_t)(co0 + lrow) * 128;
#pragma unroll
        for (int ks = 0; ks < 4; ++ks) {
            const uint32_t soff = (uint32_t)((((ks << 1) | lhi) ^ lm) << 4);
            uint32_t bh0[4], bh1[4], bl0[4], bl1[4];
            ldsm_x4(bh0, bBase + soff);
            ldsm_x4(bh1, bBase + 2048 + soff);
            ldsm_x4(bl0, bBase + 8192 + soff);
            ldsm_x4(bl1, bBase + 10240 + soff);
#pragma unroll
            for (int mf = 0; mf < 4; ++mf) {
                uint32_t ah[4];
                ldsm_x4(ah, aBase + (uint32_t)(mf * 16 * 128) + soff);
                // S * Whi
                mma_f16(acc[mf][0], ah, bh0[0], bh0[2]);
                mma_f16(acc[mf][1], ah, bh0[1], bh0[3]);
                mma_f16(acc[mf][2], ah, bh1[0], bh1[2]);
                mma_f16(acc[mf][3], ah, bh1[1], bh1[3]);
                // S * Wlo
                mma_f16(acc[mf][0], ah, bl0[0], bl0[2]);
                mma_f16(acc[mf][1], ah, bl0[1], bl0[3]);
                mma_f16(acc[mf][2], ah, bl1[0], bl1[2]);
                mma_f16(acc[mf][3], ah, bl1[1], bl1[3]);
            }
        }
        if (k + 1 < KK_)
            asm volatile("cp.async.wait_group 0;" ::: "memory");
        __syncthreads();   // protect S (and coords/W buffers) for next tap
    }

    // ---- epilogue: fragments -> gmem, add bias ----
    const int rr = (l >> 2);
    const int cbase = (l & 3) * 2;
#pragma unroll
    for (int j = 0; j < 4; ++j) {
        int cc = co0 + j * 8 + cbase;
        float b0v = bias[cc], b1v = bias[cc + 1];
        size_t plane0 = (size_t)(b * COUT_ + cc) * HW_;
        size_t plane1 = plane0 + HW_;
#pragma unroll
        for (int mf = 0; mf < 4; ++mf) {
            int px0 = pm0 + mf * 16 + rr;
            int px1 = px0 + 8;
            size_t o00 = plane0 + (size_t)(ho0 + (px0 >> 7)) * W_ + (px0 & 127);
            size_t o01 = plane1 + (size_t)(ho0 + (px0 >> 7)) * W_ + (px0 & 127);
            size_t o10 = plane0 + (size_t)(ho0 + (px1 >> 7)) * W_ + (px1 & 127);
            size_t o11 = plane1 + (size_t)(ho0 + (px1 >> 7)) * W_ + (px1 & 127);
            out[o00] = acc[mf][j][0] + b0v;
            out[o01] = acc[mf][j][1] + b1v;
            out[o10] = acc[mf][j][2] + b0v;
            out[o11] = acc[mf][j][3] + b1v;
        }
    }
}

extern "C" void kernel_launch(void* const* d_in, const int* in_sizes, int n_in,
                              void* d_out, int out_size) {
    const float* x      = (const float*)d_in[0];
    const float* offset = (const float*)d_in[1];
    const float* mask   = (const float*)d_in[2];
    const float* weight = (const float*)d_in[3];
    const float* bias   = (const float*)d_in[4];
    float* out = (float*)d_out;

    transpose_x_kernel<<<dim3(HW_ / 32, C_ / 32, B_), dim3(32, 8)>>>(x);
    prep_w_kernel<<<(KK_ * C_ * COUT_ + 255) / 256, 256>>>(weight);

    cudaFuncSetAttribute(deform_main_kernel,
                         cudaFuncAttributeMaxDynamicSharedMemorySize, SMEM_BYTES);
    deform_main_kernel<<<B_ * (H_ / 2), 256, SMEM_BYTES>>>(offset, mask, bias, out);
}